// round 5
// baseline (speedup 1.0000x reference)
#include <cuda_runtime.h>
#include <cuda_bf16.h>
#include <mma.h>
#include <math.h>

using namespace nvcuda;

#define N_NODES 100000
#define M_PAD 100032    // padded to multiple of 64 for unguarded wmma stores
#define NUM_GRAPHS 128
#define H1 4
#define C1 48
#define F1 192   // H1*C1
#define C2 96
#define D_IN 128
#define NEG_SLOPE 0.2f
#define E_MAX 1750000   // raw edges (1.6M) + self loops (100k) with slack

// ---------------- scratch (device globals; no allocation) ----------------
__device__ float g_h1[M_PAD * F1];            // x @ W1 (fp32)
__device__ __nv_bfloat16 g_h1r_hi[M_PAD * F1];  // layer1 output split bf16
__device__ __nv_bfloat16 g_h1r_lo[M_PAD * F1];
__device__ float g_asrc1[N_NODES * H1];
__device__ float g_adst1[N_NODES * H1];
__device__ float g_h2[M_PAD * C2];            // h1r @ W2 (fp32)
__device__ float g_asrc2[N_NODES];
__device__ float g_adst2[N_NODES];
__device__ float g_pool[NUM_GRAPHS * C2];
__device__ float g_cnt[NUM_GRAPHS];
__device__ int g_src[E_MAX];
__device__ int g_dst[E_MAX];
__device__ int g_batch[N_NODES];
__device__ int g_is64;
// CSR (sorted by dst)
__device__ int g_deg[N_NODES];
__device__ int g_off[N_NODES + 1];
__device__ int g_cur[N_NODES];
__device__ int g_csr_src[E_MAX];
__device__ float g_p[E_MAX * H1];             // per-edge exp scores

__device__ __forceinline__ float leaky(float s) {
    return s > 0.0f ? s : NEG_SLOPE * s;
}

// ---------------- init (zero counters only) ----------------
__global__ void init_kernel() {
    int i = blockIdx.x * blockDim.x + threadIdx.x;
    int stride = gridDim.x * blockDim.x;
    for (int k = i; k < N_NODES; k += stride) g_deg[k] = 0;
    for (int k = i; k < NUM_GRAPHS * C2; k += stride) g_pool[k] = 0.0f;
    for (int k = i; k < NUM_GRAPHS; k += stride) g_cnt[k] = 0.0f;
}

// ---------------- dtype sniff: int64 vs int32 index buffers ----------------
__global__ void sniff_kernel(const unsigned int* __restrict__ w) {
    __shared__ int any_nonzero;
    if (threadIdx.x == 0) any_nonzero = 0;
    __syncthreads();
    for (int i = threadIdx.x; i < 256; i += blockDim.x) {
        if (w[2 * i + 1] != 0u) any_nonzero = 1;
    }
    __syncthreads();
    if (threadIdx.x == 0) g_is64 = (any_nonzero == 0) ? 1 : 0;
}

// decode edge_index + self loops into int32 arrays; fused degree histogram
__global__ void decode_edges(const void* __restrict__ ei_raw, int E0) {
    int e = blockIdx.x * blockDim.x + threadIdx.x;
    int Etot = E0 + N_NODES;
    if (e >= Etot) return;
    int src, dst;
    if (e < E0) {
        if (g_is64) {
            const long long* p = (const long long*)ei_raw;
            src = (int)p[e];
            dst = (int)p[E0 + e];
        } else {
            const int* p = (const int*)ei_raw;
            src = p[e];
            dst = p[E0 + e];
        }
    } else {
        src = dst = e - E0;  // self loop
    }
    g_src[e] = src;
    g_dst[e] = dst;
    atomicAdd(&g_deg[dst], 1);
}

// batch is sorted: smem histogram, few global atomics
__global__ void decode_batch(const void* __restrict__ b_raw) {
    __shared__ int hist[NUM_GRAPHS];
    for (int i = threadIdx.x; i < NUM_GRAPHS; i += blockDim.x) hist[i] = 0;
    __syncthreads();
    int n = blockIdx.x * blockDim.x + threadIdx.x;
    if (n < N_NODES) {
        int b = g_is64 ? (int)((const long long*)b_raw)[n] : ((const int*)b_raw)[n];
        g_batch[n] = b;
        atomicAdd(&hist[b], 1);
    }
    __syncthreads();
    for (int i = threadIdx.x; i < NUM_GRAPHS; i += blockDim.x)
        if (hist[i]) atomicAdd(&g_cnt[i], (float)hist[i]);
}

// ---------------- single-block exclusive scan over degrees ----------------
__global__ void scan_kernel() {
    __shared__ int part[1024];
    int t = threadIdx.x;
    const int CH = (N_NODES + 1023) / 1024;
    int lo = t * CH, hi = min(lo + CH, N_NODES);
    int s = 0;
    for (int i = lo; i < hi; i++) s += g_deg[i];
    part[t] = s;
    __syncthreads();
    for (int o = 1; o < 1024; o <<= 1) {
        int v = (t >= o) ? part[t - o] : 0;
        __syncthreads();
        part[t] += v;
        __syncthreads();
    }
    int base = (t > 0) ? part[t - 1] : 0;
    for (int i = lo; i < hi; i++) {
        g_off[i] = base;
        g_cur[i] = base;
        base += g_deg[i];
    }
    if (t == 1023) g_off[N_NODES] = part[1023];
}

__global__ void scatter_kernel(int Etot) {
    int e = blockIdx.x * blockDim.x + threadIdx.x;
    if (e >= Etot) return;
    int pos = atomicAdd(&g_cur[g_dst[e]], 1);
    g_csr_src[pos] = g_src[e];
}

// ---------------- split-bf16 tensor-core GEMM --------------------------------
// C[M_PAD,N] = A[M,K] @ B[K,N]  via  Ah*Bh + Ah*Bl + Al*Bh   (fp32 accumulate)
// Block: 384 threads = 12 warps (2 rows x 6 cols), tile 64x96, BK=32.
// A_IS_F32: convert fp32 A inline; else read pre-split bf16 hi/lo (padded rows valid).
template <int KDIM, bool A_IS_F32>
__global__ void __launch_bounds__(384) wgemm_kernel(
    const float* __restrict__ A,
    const __nv_bfloat16* __restrict__ Ah_pre, const __nv_bfloat16* __restrict__ Al_pre,
    const float* __restrict__ B, float* __restrict__ C, int M, int N) {
    __shared__ __nv_bfloat16 Ah[64 * 32];
    __shared__ __nv_bfloat16 Al[64 * 32];
    __shared__ __nv_bfloat16 Bh[32 * 96];
    __shared__ __nv_bfloat16 Bl[32 * 96];

    int tid = threadIdx.x;
    int wid = tid >> 5;
    int wrow = wid / 6;        // 0..1
    int wcol = wid % 6;        // 0..5
    int row0 = blockIdx.y * 64;
    int col0 = blockIdx.x * 96;

    wmma::fragment<wmma::accumulator, 16, 16, 16, float> acc[2];
    wmma::fill_fragment(acc[0], 0.0f);
    wmma::fill_fragment(acc[1], 0.0f);

    for (int k0 = 0; k0 < KDIM; k0 += 32) {
        // stage A (64x32)
        for (int it = tid; it < 64 * 32; it += 384) {
            int r = it >> 5, c = it & 31;
            int gr = row0 + r;
            if (A_IS_F32) {
                float v = (gr < M) ? A[(size_t)gr * KDIM + k0 + c] : 0.0f;
                __nv_bfloat16 hi = __float2bfloat16(v);
                Ah[it] = hi;
                Al[it] = __float2bfloat16(v - __bfloat162float(hi));
            } else {
                size_t gi = (size_t)gr * KDIM + k0 + c;
                Ah[it] = Ah_pre[gi];
                Al[it] = Al_pre[gi];
            }
        }
        // stage B (32x96)
        for (int it = tid; it < 32 * 96; it += 384) {
            int r = it / 96, c = it % 96;
            float v = B[(size_t)(k0 + r) * N + col0 + c];
            __nv_bfloat16 hi = __float2bfloat16(v);
            Bh[it] = hi;
            Bl[it] = __float2bfloat16(v - __bfloat162float(hi));
        }
        __syncthreads();

#pragma unroll
        for (int kk = 0; kk < 32; kk += 16) {
            wmma::fragment<wmma::matrix_a, 16, 16, 16, __nv_bfloat16, wmma::row_major> ah0, ah1, al0, al1;
            wmma::fragment<wmma::matrix_b, 16, 16, 16, __nv_bfloat16, wmma::row_major> bh, bl;
            wmma::load_matrix_sync(ah0, &Ah[(wrow * 32 + 0) * 32 + kk], 32);
            wmma::load_matrix_sync(ah1, &Ah[(wrow * 32 + 16) * 32 + kk], 32);
            wmma::load_matrix_sync(al0, &Al[(wrow * 32 + 0) * 32 + kk], 32);
            wmma::load_matrix_sync(al1, &Al[(wrow * 32 + 16) * 32 + kk], 32);
            wmma::load_matrix_sync(bh, &Bh[kk * 96 + wcol * 16], 96);
            wmma::load_matrix_sync(bl, &Bl[kk * 96 + wcol * 16], 96);
            wmma::mma_sync(acc[0], ah0, bh, acc[0]);
            wmma::mma_sync(acc[0], ah0, bl, acc[0]);
            wmma::mma_sync(acc[0], al0, bh, acc[0]);
            wmma::mma_sync(acc[1], ah1, bh, acc[1]);
            wmma::mma_sync(acc[1], ah1, bl, acc[1]);
            wmma::mma_sync(acc[1], al1, bh, acc[1]);
        }
        __syncthreads();
    }

#pragma unroll
    for (int i = 0; i < 2; i++) {
        size_t r = (size_t)(row0 + wrow * 32 + i * 16);
        wmma::store_matrix_sync(&C[r * N + col0 + wcol * 16], acc[i], N, wmma::mem_row_major);
    }
}

// ---------------- attention scalars ----------------
__global__ void attn1_kernel(const float* __restrict__ a_src, const float* __restrict__ a_dst) {
    int idx = blockIdx.x * blockDim.x + threadIdx.x;  // node*4 + head
    if (idx >= N_NODES * H1) return;
    int n = idx >> 2, h = idx & 3;
    const float* hp = &g_h1[(size_t)n * F1 + h * C1];
    const float* ws = &a_src[h * C1];
    const float* wd = &a_dst[h * C1];
    float ss = 0.0f, sd = 0.0f;
#pragma unroll
    for (int j = 0; j < C1; j++) {
        float v = hp[j];
        ss += v * ws[j];
        sd += v * wd[j];
    }
    g_asrc1[idx] = ss;
    g_adst1[idx] = sd;
}

__global__ void attn2_kernel(const float* __restrict__ a_src, const float* __restrict__ a_dst) {
    int w = (blockIdx.x * blockDim.x + threadIdx.x) >> 5;
    int lane = threadIdx.x & 31;
    if (w >= N_NODES) return;
    const float* hp = &g_h2[(size_t)w * C2];
    float ss = 0.0f, sd = 0.0f;
#pragma unroll
    for (int k = 0; k < 3; k++) {
        int j = lane + 32 * k;
        float v = hp[j];
        ss += v * a_src[j];
        sd += v * a_dst[j];
    }
#pragma unroll
    for (int o = 16; o > 0; o >>= 1) {
        ss += __shfl_down_sync(0xffffffffu, ss, o);
        sd += __shfl_down_sync(0xffffffffu, sd, o);
    }
    if (lane == 0) {
        g_asrc2[w] = ss;
        g_adst2[w] = sd;
    }
}

// ---------------- layer 1 fused: softmax + aggregate + bias + relu (warp/node) ----
// output written as split bf16 (GEMM2 input)
__global__ void gat1_kernel(const float* __restrict__ b1) {
    int node = (blockIdx.x * blockDim.x + threadIdx.x) >> 5;
    int lane = threadIdx.x & 31;
    if (node >= N_NODES) return;
    int start = g_off[node], end = g_off[node + 1];

    float4 ad = *(const float4*)&g_adst1[node * H1];

    // pass A: exp scores + denominator
    float4 den = make_float4(0.f, 0.f, 0.f, 0.f);
    for (int idx = start + lane; idx < end; idx += 32) {
        int src = g_csr_src[idx];
        float4 as = *(const float4*)&g_asrc1[src * H1];
        float4 p;
        p.x = __expf(leaky(as.x + ad.x));
        p.y = __expf(leaky(as.y + ad.y));
        p.z = __expf(leaky(as.z + ad.z));
        p.w = __expf(leaky(as.w + ad.w));
        *(float4*)&g_p[(size_t)idx * 4] = p;
        den.x += p.x; den.y += p.y; den.z += p.z; den.w += p.w;
    }
#pragma unroll
    for (int o = 16; o > 0; o >>= 1) {
        den.x += __shfl_xor_sync(0xffffffffu, den.x, o);
        den.y += __shfl_xor_sync(0xffffffffu, den.y, o);
        den.z += __shfl_xor_sync(0xffffffffu, den.z, o);
        den.w += __shfl_xor_sync(0xffffffffu, den.w, o);
    }
    float inv0 = 1.0f / den.x, inv1 = 1.0f / den.y, inv2 = 1.0f / den.z, inv3 = 1.0f / den.w;

    // pass B: weighted aggregation
    float acc[6] = {0.f, 0.f, 0.f, 0.f, 0.f, 0.f};
    for (int idx = start; idx < end; idx++) {
        int src = g_csr_src[idx];
        float4 p4 = *(const float4*)&g_p[(size_t)idx * 4];
        float a0 = p4.x * inv0, a1 = p4.y * inv1, a2 = p4.z * inv2, a3 = p4.w * inv3;
        const float* hp = &g_h1[(size_t)src * F1];
#pragma unroll
        for (int k = 0; k < 6; k++) {
            int c = k * 32 + lane;
            float al = (c < 48) ? a0 : (c < 96) ? a1 : (c < 144) ? a2 : a3;
            acc[k] += hp[c] * al;
        }
    }
#pragma unroll
    for (int k = 0; k < 6; k++) {
        int c = k * 32 + lane;
        float v = fmaxf(acc[k] + b1[c], 0.0f);
        __nv_bfloat16 hi = __float2bfloat16(v);
        size_t o = (size_t)node * F1 + c;
        g_h1r_hi[o] = hi;
        g_h1r_lo[o] = __float2bfloat16(v - __bfloat162float(hi));
    }
}

// ---------------- layer 2 fused: softmax + aggregate + bias + relu + pool ----
__global__ void gat2_kernel(const float* __restrict__ b2) {
    int node = (blockIdx.x * blockDim.x + threadIdx.x) >> 5;
    int lane = threadIdx.x & 31;
    if (node >= N_NODES) return;
    int start = g_off[node], end = g_off[node + 1];

    float ad = g_adst2[node];
    float den = 0.0f;
    for (int idx = start + lane; idx < end; idx += 32) {
        int src = g_csr_src[idx];
        float p = __expf(leaky(g_asrc2[src] + ad));
        g_p[idx] = p;
        den += p;
    }
#pragma unroll
    for (int o = 16; o > 0; o >>= 1) den += __shfl_xor_sync(0xffffffffu, den, o);
    float inv = 1.0f / den;

    float acc[3] = {0.f, 0.f, 0.f};
    for (int idx = start; idx < end; idx++) {
        int src = g_csr_src[idx];
        float alpha = g_p[idx] * inv;
        const float* hp = &g_h2[(size_t)src * C2];
#pragma unroll
        for (int k = 0; k < 3; k++) acc[k] += hp[k * 32 + lane] * alpha;
    }
    int gp = g_batch[node] * C2;
#pragma unroll
    for (int k = 0; k < 3; k++) {
        int c = k * 32 + lane;
        float v = fmaxf(acc[k] + b2[c], 0.0f);
        atomicAdd(&g_pool[gp + c], v);
    }
}

// ---------------- final MLP: one block per graph ----------------
__global__ void mlp_kernel(const float* __restrict__ fc1_w, const float* __restrict__ fc1_b,
                           const float* __restrict__ fc2_w, const float* __restrict__ fc2_b,
                           float* __restrict__ out) {
    __shared__ float p[C2];
    __shared__ float z[192];
    int g = blockIdx.x;
    int t = threadIdx.x;  // 192 threads
    float inv = 1.0f / fmaxf(g_cnt[g], 1.0f);
    if (t < C2) p[t] = g_pool[g * C2 + t] * inv;
    __syncthreads();
    float acc = fc1_b[t];
#pragma unroll
    for (int k = 0; k < C2; k++) acc += p[k] * fc1_w[k * 192 + t];
    z[t] = fmaxf(acc, 0.0f);
    __syncthreads();
    if (t < C2) {
        float o = fc2_b[t];
#pragma unroll
        for (int k = 0; k < 192; k++) o += z[k] * fc2_w[k * C2 + t];
        out[g * C2 + t] = o;
    }
}

// ---------------- host launch ----------------
extern "C" void kernel_launch(void* const* d_in, const int* in_sizes, int n_in,
                              void* d_out, int out_size) {
    const float* x = (const float*)d_in[0];
    const void* ei_raw = d_in[1];
    const void* batch_raw = d_in[2];
    const float* W1 = (const float*)d_in[3];
    const float* a_src1 = (const float*)d_in[4];
    const float* a_dst1 = (const float*)d_in[5];
    const float* b1 = (const float*)d_in[6];
    const float* W2 = (const float*)d_in[7];
    const float* a_src2 = (const float*)d_in[8];
    const float* a_dst2 = (const float*)d_in[9];
    const float* b2 = (const float*)d_in[10];
    const float* fc1_w = (const float*)d_in[11];
    const float* fc1_b = (const float*)d_in[12];
    const float* fc2_w = (const float*)d_in[13];
    const float* fc2_b = (const float*)d_in[14];
    float* out = (float*)d_out;

    int E0 = in_sizes[1] / 2;
    int Etot = E0 + N_NODES;

    float *h1p, *h2p;
    __nv_bfloat16 *h1hip, *h1lop;
    cudaGetSymbolAddress((void**)&h1p, g_h1);
    cudaGetSymbolAddress((void**)&h2p, g_h2);
    cudaGetSymbolAddress((void**)&h1hip, g_h1r_hi);
    cudaGetSymbolAddress((void**)&h1lop, g_h1r_lo);

    // graph preprocessing
    init_kernel<<<256, 256>>>();
    sniff_kernel<<<1, 256>>>((const unsigned int*)ei_raw);
    decode_edges<<<(Etot + 255) / 256, 256>>>(ei_raw, E0);
    decode_batch<<<(N_NODES + 255) / 256, 256>>>(batch_raw);
    scan_kernel<<<1, 1024>>>();
    scatter_kernel<<<(Etot + 255) / 256, 256>>>(Etot);

    // layer 1 GEMM: [100000,128] @ [128,192] -> g_h1
    {
        dim3 grid(F1 / 96, M_PAD / 64);
        wgemm_kernel<D_IN, true><<<grid, 384>>>(x, nullptr, nullptr, W1, h1p, N_NODES, F1);
    }
    attn1_kernel<<<(N_NODES * H1 + 255) / 256, 256>>>(a_src1, a_dst1);
    gat1_kernel<<<(N_NODES + 7) / 8, 256>>>(b1);

    // layer 2 GEMM: [100032,192](bf16 split) @ [192,96] -> g_h2
    {
        dim3 grid(C2 / 96, M_PAD / 64);
        wgemm_kernel<F1, false><<<grid, 384>>>(nullptr, h1hip, h1lop, W2, h2p, N_NODES, C2);
    }
    attn2_kernel<<<(N_NODES * 32 + 255) / 256, 256>>>(a_src2, a_dst2);
    gat2_kernel<<<(N_NODES + 7) / 8, 256>>>(b2);

    // MLP head
    mlp_kernel<<<NUM_GRAPHS, 192>>>(fc1_w, fc1_b, fc2_w, fc2_b, out);
}

// round 6
// speedup vs baseline: 1.0938x; 1.0938x over previous
#include <cuda_runtime.h>
#include <math.h>

#define N_NODES 100000
#define M_PAD 100096    // multiple of 256 for unguarded GEMM stores
#define NUM_GRAPHS 128
#define H1 4
#define C1 48
#define F1 192   // H1*C1
#define C2 96
#define D_IN 128
#define NEG_SLOPE 0.2f
#define E_MAX 1750000

// ---------------- scratch (device globals; no allocation) ----------------
__device__ float g_h1[M_PAD * F1];      // x @ W1
__device__ float g_h1r[M_PAD * F1];     // layer1 output (relu'd); padded rows stay 0
__device__ float g_asrc1[N_NODES * H1];
__device__ float g_adst1[N_NODES * H1];
__device__ float g_h2[M_PAD * C2];      // h1r @ W2
__device__ float g_asrc2[N_NODES];
__device__ float g_adst2[N_NODES];
__device__ float g_pool[NUM_GRAPHS * C2];
__device__ float g_cnt[NUM_GRAPHS];
__device__ int g_src[E_MAX];
__device__ int g_dst[E_MAX];
__device__ int g_batch[N_NODES];
__device__ int g_is64;
__device__ int g_deg[N_NODES];
__device__ int g_off[N_NODES + 1];
__device__ int g_cur[N_NODES];
__device__ int g_csr_src[E_MAX];
__device__ float g_p[E_MAX * H1];

__device__ __forceinline__ float leaky(float s) {
    return s > 0.0f ? s : NEG_SLOPE * s;
}

// ---------------- packed fp32x2 FMA helpers (Blackwell f32x2 pipe) ----------
__device__ __forceinline__ unsigned long long splat2(float a) {
    unsigned long long r;
    asm("mov.b64 %0, {%1, %1};" : "=l"(r) : "f"(a));
    return r;
}
__device__ __forceinline__ void ffma2(unsigned long long& d, unsigned long long a,
                                      unsigned long long b) {
    asm("fma.rn.f32x2 %0, %1, %2, %0;" : "+l"(d) : "l"(a), "l"(b));
}
__device__ __forceinline__ float2 unpack2(unsigned long long v) {
    float2 f;
    asm("mov.b64 {%0, %1}, %2;" : "=f"(f.x), "=f"(f.y) : "l"(v));
    return f;
}

// ---------------- init ----------------
__global__ void init_kernel() {
    int i = blockIdx.x * blockDim.x + threadIdx.x;
    int stride = gridDim.x * blockDim.x;
    for (int k = i; k < N_NODES; k += stride) g_deg[k] = 0;
    for (int k = i; k < NUM_GRAPHS * C2; k += stride) g_pool[k] = 0.0f;
    for (int k = i; k < NUM_GRAPHS; k += stride) g_cnt[k] = 0.0f;
}

// ---------------- dtype sniff ----------------
__global__ void sniff_kernel(const unsigned int* __restrict__ w) {
    __shared__ int any_nonzero;
    if (threadIdx.x == 0) any_nonzero = 0;
    __syncthreads();
    for (int i = threadIdx.x; i < 256; i += blockDim.x) {
        if (w[2 * i + 1] != 0u) any_nonzero = 1;
    }
    __syncthreads();
    if (threadIdx.x == 0) g_is64 = (any_nonzero == 0) ? 1 : 0;
}

__global__ void decode_edges(const void* __restrict__ ei_raw, int E0) {
    int e = blockIdx.x * blockDim.x + threadIdx.x;
    int Etot = E0 + N_NODES;
    if (e >= Etot) return;
    int src, dst;
    if (e < E0) {
        if (g_is64) {
            const long long* p = (const long long*)ei_raw;
            src = (int)p[e];
            dst = (int)p[E0 + e];
        } else {
            const int* p = (const int*)ei_raw;
            src = p[e];
            dst = p[E0 + e];
        }
    } else {
        src = dst = e - E0;
    }
    g_src[e] = src;
    g_dst[e] = dst;
    atomicAdd(&g_deg[dst], 1);
}

__global__ void decode_batch(const void* __restrict__ b_raw) {
    __shared__ int hist[NUM_GRAPHS];
    for (int i = threadIdx.x; i < NUM_GRAPHS; i += blockDim.x) hist[i] = 0;
    __syncthreads();
    int n = blockIdx.x * blockDim.x + threadIdx.x;
    if (n < N_NODES) {
        int b = g_is64 ? (int)((const long long*)b_raw)[n] : ((const int*)b_raw)[n];
        g_batch[n] = b;
        atomicAdd(&hist[b], 1);
    }
    __syncthreads();
    for (int i = threadIdx.x; i < NUM_GRAPHS; i += blockDim.x)
        if (hist[i]) atomicAdd(&g_cnt[i], (float)hist[i]);
}

__global__ void scan_kernel() {
    __shared__ int part[1024];
    int t = threadIdx.x;
    const int CH = (N_NODES + 1023) / 1024;
    int lo = t * CH, hi = min(lo + CH, N_NODES);
    int s = 0;
    for (int i = lo; i < hi; i++) s += g_deg[i];
    part[t] = s;
    __syncthreads();
    for (int o = 1; o < 1024; o <<= 1) {
        int v = (t >= o) ? part[t - o] : 0;
        __syncthreads();
        part[t] += v;
        __syncthreads();
    }
    int base = (t > 0) ? part[t - 1] : 0;
    for (int i = lo; i < hi; i++) {
        g_off[i] = base;
        g_cur[i] = base;
        base += g_deg[i];
    }
    if (t == 1023) g_off[N_NODES] = part[1023];
}

__global__ void scatter_kernel(int Etot) {
    int e = blockIdx.x * blockDim.x + threadIdx.x;
    if (e >= Etot) return;
    int pos = atomicAdd(&g_cur[g_dst[e]], 1);
    g_csr_src[pos] = g_src[e];
}

// ---------------- FFMA2 SGEMM: C[M_PAD,NDIM] = A[M,KDIM] @ B[KDIM,NDIM] ------
// 8x8 micro-tile per thread; packed f32x2 FMA. TBM = (NT/(TBN/8))*8, rows padded.
template <int TBM, int TBN, int NT, int KDIM, int NDIM>
__global__ void __launch_bounds__(NT) sgemm2_kernel(const float* __restrict__ A,
                                                    const float* __restrict__ B,
                                                    float* __restrict__ C, int M) {
    const int TX = TBN / 8;
    __shared__ float As[32][TBM + 4];  // transposed A tile
    __shared__ float Bs[32][TBN];

    int tid = threadIdx.x;
    int tx = tid % TX;
    int ty = tid / TX;
    int row0 = blockIdx.y * TBM;
    int col0 = blockIdx.x * TBN;

    unsigned long long acc[8][4];
#pragma unroll
    for (int i = 0; i < 8; i++)
#pragma unroll
        for (int p = 0; p < 4; p++) acc[i][p] = 0ull;

    for (int k0 = 0; k0 < KDIM; k0 += 32) {
        // stage A (TBM x 32), transposed
        for (int i4 = tid; i4 < TBM * 8; i4 += NT) {
            int kc = i4 % 8;
            int r = i4 / 8;
            int gr = row0 + r;
            float4 v = (gr < M) ? *(const float4*)&A[(size_t)gr * KDIM + k0 + kc * 4]
                                : make_float4(0.f, 0.f, 0.f, 0.f);
            As[kc * 4 + 0][r] = v.x;
            As[kc * 4 + 1][r] = v.y;
            As[kc * 4 + 2][r] = v.z;
            As[kc * 4 + 3][r] = v.w;
        }
        // stage B (32 x TBN)
        for (int i4 = tid; i4 < 8 * TBN; i4 += NT) {
            int c4 = i4 % (TBN / 4);
            int r = i4 / (TBN / 4);
            *(float4*)&Bs[r][c4 * 4] = *(const float4*)&B[(size_t)(k0 + r) * NDIM + col0 + c4 * 4];
        }
        __syncthreads();

#pragma unroll 8
        for (int k = 0; k < 32; k++) {
            float4 a0 = *(const float4*)&As[k][ty * 8];
            float4 a1 = *(const float4*)&As[k][ty * 8 + 4];
            unsigned long long pa[8];
            pa[0] = splat2(a0.x); pa[1] = splat2(a0.y);
            pa[2] = splat2(a0.z); pa[3] = splat2(a0.w);
            pa[4] = splat2(a1.x); pa[5] = splat2(a1.y);
            pa[6] = splat2(a1.z); pa[7] = splat2(a1.w);
            ulonglong2 b0 = *(const ulonglong2*)&Bs[k][tx * 8];
            ulonglong2 b1 = *(const ulonglong2*)&Bs[k][tx * 8 + 4];
            unsigned long long bv[4] = {b0.x, b0.y, b1.x, b1.y};
#pragma unroll
            for (int i = 0; i < 8; i++)
#pragma unroll
                for (int p = 0; p < 4; p++) ffma2(acc[i][p], pa[i], bv[p]);
        }
        __syncthreads();
    }

#pragma unroll
    for (int i = 0; i < 8; i++) {
        size_t r = (size_t)(row0 + ty * 8 + i);
        float2 v0 = unpack2(acc[i][0]), v1 = unpack2(acc[i][1]);
        float2 v2 = unpack2(acc[i][2]), v3 = unpack2(acc[i][3]);
        *(float4*)&C[r * NDIM + col0 + tx * 8] = make_float4(v0.x, v0.y, v1.x, v1.y);
        *(float4*)&C[r * NDIM + col0 + tx * 8 + 4] = make_float4(v2.x, v2.y, v3.x, v3.y);
    }
}

// ---------------- attention scalars ----------------
__global__ void attn1_kernel(const float* __restrict__ a_src, const float* __restrict__ a_dst) {
    int idx = blockIdx.x * blockDim.x + threadIdx.x;
    if (idx >= N_NODES * H1) return;
    int n = idx >> 2, h = idx & 3;
    const float* hp = &g_h1[(size_t)n * F1 + h * C1];
    const float* ws = &a_src[h * C1];
    const float* wd = &a_dst[h * C1];
    float ss = 0.0f, sd = 0.0f;
#pragma unroll
    for (int j = 0; j < C1; j++) {
        float v = hp[j];
        ss += v * ws[j];
        sd += v * wd[j];
    }
    g_asrc1[idx] = ss;
    g_adst1[idx] = sd;
}

__global__ void attn2_kernel(const float* __restrict__ a_src, const float* __restrict__ a_dst) {
    int w = (blockIdx.x * blockDim.x + threadIdx.x) >> 5;
    int lane = threadIdx.x & 31;
    if (w >= N_NODES) return;
    const float* hp = &g_h2[(size_t)w * C2];
    float ss = 0.0f, sd = 0.0f;
#pragma unroll
    for (int k = 0; k < 3; k++) {
        int j = lane + 32 * k;
        float v = hp[j];
        ss += v * a_src[j];
        sd += v * a_dst[j];
    }
#pragma unroll
    for (int o = 16; o > 0; o >>= 1) {
        ss += __shfl_down_sync(0xffffffffu, ss, o);
        sd += __shfl_down_sync(0xffffffffu, sd, o);
    }
    if (lane == 0) {
        g_asrc2[w] = ss;
        g_adst2[w] = sd;
    }
}

// ---------------- layer 1 fused: softmax + aggregate + bias + relu (warp/node) ----
// lane owns channels [lane*4, lane*4+4) and [128+lane*2, 128+lane*2+2);
// head boundaries (48,96,144) are multiples of the vector widths -> uniform head per load.
__global__ void gat1_kernel(const float* __restrict__ b1) {
    int node = (blockIdx.x * blockDim.x + threadIdx.x) >> 5;
    int lane = threadIdx.x & 31;
    if (node >= N_NODES) return;
    int start = g_off[node], end = g_off[node + 1];

    float4 ad = *(const float4*)&g_adst1[node * H1];

    // pass A: exp scores + denominator
    float4 den = make_float4(0.f, 0.f, 0.f, 0.f);
    for (int idx = start + lane; idx < end; idx += 32) {
        int src = g_csr_src[idx];
        float4 as = *(const float4*)&g_asrc1[src * H1];
        float4 p;
        p.x = __expf(leaky(as.x + ad.x));
        p.y = __expf(leaky(as.y + ad.y));
        p.z = __expf(leaky(as.z + ad.z));
        p.w = __expf(leaky(as.w + ad.w));
        *(float4*)&g_p[(size_t)idx * 4] = p;
        den.x += p.x; den.y += p.y; den.z += p.z; den.w += p.w;
    }
#pragma unroll
    for (int o = 16; o > 0; o >>= 1) {
        den.x += __shfl_xor_sync(0xffffffffu, den.x, o);
        den.y += __shfl_xor_sync(0xffffffffu, den.y, o);
        den.z += __shfl_xor_sync(0xffffffffu, den.z, o);
        den.w += __shfl_xor_sync(0xffffffffu, den.w, o);
    }
    float inv0 = 1.0f / den.x, inv1 = 1.0f / den.y, inv2 = 1.0f / den.z, inv3 = 1.0f / den.w;

    int c4 = lane * 4;          // channels c4..c4+3, head hA
    int c2 = 128 + lane * 2;    // channels c2..c2+1, head hB
    int hA = c4 / C1;
    int hB = c2 / C1;
    float invA = (hA == 0) ? inv0 : (hA == 1) ? inv1 : inv2;  // hA in {0,1,2}
    float invB = (hB == 2) ? inv2 : inv3;                     // hB in {2,3}

    // pass B: weighted aggregation (vectorized gathers)
    float4 acc4 = make_float4(0.f, 0.f, 0.f, 0.f);
    float2 acc2 = make_float2(0.f, 0.f);
#pragma unroll 2
    for (int idx = start; idx < end; idx++) {
        int src = g_csr_src[idx];
        float4 p4 = *(const float4*)&g_p[(size_t)idx * 4];
        float pA = (hA == 0) ? p4.x : (hA == 1) ? p4.y : p4.z;
        float pB = (hB == 2) ? p4.z : p4.w;
        float alA = pA * invA;
        float alB = pB * invB;
        const float* hp = &g_h1[(size_t)src * F1];
        float4 hv4 = *(const float4*)&hp[c4];
        float2 hv2 = *(const float2*)&hp[c2];
        acc4.x += hv4.x * alA; acc4.y += hv4.y * alA;
        acc4.z += hv4.z * alA; acc4.w += hv4.w * alA;
        acc2.x += hv2.x * alB; acc2.y += hv2.y * alB;
    }
    float4 bb4 = *(const float4*)&b1[c4];
    float2 bb2 = *(const float2*)&b1[c2];
    float4 o4 = make_float4(fmaxf(acc4.x + bb4.x, 0.f), fmaxf(acc4.y + bb4.y, 0.f),
                            fmaxf(acc4.z + bb4.z, 0.f), fmaxf(acc4.w + bb4.w, 0.f));
    float2 o2 = make_float2(fmaxf(acc2.x + bb2.x, 0.f), fmaxf(acc2.y + bb2.y, 0.f));
    *(float4*)&g_h1r[(size_t)node * F1 + c4] = o4;
    *(float2*)&g_h1r[(size_t)node * F1 + c2] = o2;
}

// ---------------- layer 2 fused: softmax + aggregate + bias + relu + pool ----
// lane owns channels [lane*2, lane*2+2) and 64+lane.
__global__ void gat2_kernel(const float* __restrict__ b2) {
    int node = (blockIdx.x * blockDim.x + threadIdx.x) >> 5;
    int lane = threadIdx.x & 31;
    if (node >= N_NODES) return;
    int start = g_off[node], end = g_off[node + 1];

    float ad = g_adst2[node];
    float den = 0.0f;
    for (int idx = start + lane; idx < end; idx += 32) {
        int src = g_csr_src[idx];
        float p = __expf(leaky(g_asrc2[src] + ad));
        g_p[idx] = p;
        den += p;
    }
#pragma unroll
    for (int o = 16; o > 0; o >>= 1) den += __shfl_xor_sync(0xffffffffu, den, o);
    float inv = 1.0f / den;

    int c2 = lane * 2;
    int cs = 64 + lane;
    float2 acc2 = make_float2(0.f, 0.f);
    float accs = 0.0f;
#pragma unroll 2
    for (int idx = start; idx < end; idx++) {
        int src = g_csr_src[idx];
        float alpha = g_p[idx] * inv;
        const float* hp = &g_h2[(size_t)src * C2];
        float2 hv2 = *(const float2*)&hp[c2];
        float hvs = hp[cs];
        acc2.x += hv2.x * alpha;
        acc2.y += hv2.y * alpha;
        accs += hvs * alpha;
    }
    int gp = g_batch[node] * C2;
    atomicAdd(&g_pool[gp + c2], fmaxf(acc2.x + b2[c2], 0.0f));
    atomicAdd(&g_pool[gp + c2 + 1], fmaxf(acc2.y + b2[c2 + 1], 0.0f));
    atomicAdd(&g_pool[gp + cs], fmaxf(accs + b2[cs], 0.0f));
}

// ---------------- final MLP: one block per graph ----------------
__global__ void mlp_kernel(const float* __restrict__ fc1_w, const float* __restrict__ fc1_b,
                           const float* __restrict__ fc2_w, const float* __restrict__ fc2_b,
                           float* __restrict__ out) {
    __shared__ float p[C2];
    __shared__ float z[192];
    int g = blockIdx.x;
    int t = threadIdx.x;
    float inv = 1.0f / fmaxf(g_cnt[g], 1.0f);
    if (t < C2) p[t] = g_pool[g * C2 + t] * inv;
    __syncthreads();
    float acc = fc1_b[t];
#pragma unroll
    for (int k = 0; k < C2; k++) acc += p[k] * fc1_w[k * 192 + t];
    z[t] = fmaxf(acc, 0.0f);
    __syncthreads();
    if (t < C2) {
        float o = fc2_b[t];
#pragma unroll
        for (int k = 0; k < 192; k++) o += z[k] * fc2_w[k * C2 + t];
        out[g * C2 + t] = o;
    }
}

// ---------------- host launch ----------------
extern "C" void kernel_launch(void* const* d_in, const int* in_sizes, int n_in,
                              void* d_out, int out_size) {
    const float* x = (const float*)d_in[0];
    const void* ei_raw = d_in[1];
    const void* batch_raw = d_in[2];
    const float* W1 = (const float*)d_in[3];
    const float* a_src1 = (const float*)d_in[4];
    const float* a_dst1 = (const float*)d_in[5];
    const float* b1 = (const float*)d_in[6];
    const float* W2 = (const float*)d_in[7];
    const float* a_src2 = (const float*)d_in[8];
    const float* a_dst2 = (const float*)d_in[9];
    const float* b2 = (const float*)d_in[10];
    const float* fc1_w = (const float*)d_in[11];
    const float* fc1_b = (const float*)d_in[12];
    const float* fc2_w = (const float*)d_in[13];
    const float* fc2_b = (const float*)d_in[14];
    float* out = (float*)d_out;

    int E0 = in_sizes[1] / 2;
    int Etot = E0 + N_NODES;

    float *h1p, *h1rp, *h2p;
    cudaGetSymbolAddress((void**)&h1p, g_h1);
    cudaGetSymbolAddress((void**)&h1rp, g_h1r);
    cudaGetSymbolAddress((void**)&h2p, g_h2);

    // graph preprocessing
    init_kernel<<<256, 256>>>();
    sniff_kernel<<<1, 256>>>((const unsigned int*)ei_raw);
    decode_edges<<<(Etot + 255) / 256, 256>>>(ei_raw, E0);
    decode_batch<<<(N_NODES + 255) / 256, 256>>>(batch_raw);
    scan_kernel<<<1, 1024>>>();
    scatter_kernel<<<(Etot + 255) / 256, 256>>>(Etot);

    // layer 1 GEMM: [100000,128] @ [128,192]
    {
        dim3 grid(F1 / 64, M_PAD / 256);
        sgemm2_kernel<256, 64, 256, D_IN, F1><<<grid, 256>>>(x, W1, h1p, N_NODES);
    }
    attn1_kernel<<<(N_NODES * H1 + 255) / 256, 256>>>(a_src1, a_dst1);
    gat1_kernel<<<(N_NODES + 7) / 8, 256>>>(b1);

    // layer 2 GEMM: [100000,192] @ [192,96]
    {
        dim3 grid(C2 / 96, M_PAD / 128);
        sgemm2_kernel<128, 96, 192, F1, C2><<<grid, 192>>>(h1rp, W2, h2p, N_NODES);
    }
    attn2_kernel<<<(N_NODES * 32 + 255) / 256, 256>>>(a_src2, a_dst2);
    gat2_kernel<<<(N_NODES + 7) / 8, 256>>>(b2);

    // MLP head
    mlp_kernel<<<NUM_GRAPHS, 192>>>(fc1_w, fc1_b, fc2_w, fc2_b, out);
}

// round 7
// speedup vs baseline: 1.1682x; 1.0680x over previous
#include <cuda_runtime.h>
#include <math.h>

#define N_NODES 100000
#define M_PAD 100096    // multiple of 256
#define NUM_GRAPHS 128
#define H1 4
#define C1 48
#define F1 192   // H1*C1
#define C2 96
#define D_IN 128
#define NEG_SLOPE 0.2f
#define E_MAX 1750000

// ---------------- scratch (device globals; no allocation) ----------------
__device__ float g_h1[M_PAD * F1];      // x @ W1
__device__ float g_h1r[M_PAD * F1];     // layer1 output (relu'd); padded rows stay 0
__device__ float g_asrc1[N_NODES * H1];
__device__ float g_adst1[N_NODES * H1];
__device__ float g_h2[M_PAD * C2];      // h1r @ W2
__device__ float g_asrc2[N_NODES];
__device__ float g_adst2[N_NODES];
__device__ float g_pool[NUM_GRAPHS * C2];
__device__ float g_cnt[NUM_GRAPHS];
__device__ int g_src[E_MAX];
__device__ int g_dst[E_MAX];
__device__ int g_batch[N_NODES];
__device__ int g_is64;
__device__ int g_deg[N_NODES];
__device__ int g_off[N_NODES + 1];
__device__ int g_cur[N_NODES];
__device__ int g_csr_src[E_MAX];
__device__ float g_p[E_MAX * H1];

__device__ __forceinline__ float leaky(float s) {
    return s > 0.0f ? s : NEG_SLOPE * s;
}

// ---------------- init ----------------
__global__ void init_kernel() {
    int i = blockIdx.x * blockDim.x + threadIdx.x;
    int stride = gridDim.x * blockDim.x;
    for (int k = i; k < N_NODES; k += stride) g_deg[k] = 0;
    for (int k = i; k < NUM_GRAPHS * C2; k += stride) g_pool[k] = 0.0f;
    for (int k = i; k < NUM_GRAPHS; k += stride) g_cnt[k] = 0.0f;
}

// ---------------- dtype sniff ----------------
__global__ void sniff_kernel(const unsigned int* __restrict__ w) {
    __shared__ int any_nonzero;
    if (threadIdx.x == 0) any_nonzero = 0;
    __syncthreads();
    for (int i = threadIdx.x; i < 256; i += blockDim.x) {
        if (w[2 * i + 1] != 0u) any_nonzero = 1;
    }
    __syncthreads();
    if (threadIdx.x == 0) g_is64 = (any_nonzero == 0) ? 1 : 0;
}

__global__ void decode_edges(const void* __restrict__ ei_raw, int E0) {
    int e = blockIdx.x * blockDim.x + threadIdx.x;
    int Etot = E0 + N_NODES;
    if (e >= Etot) return;
    int src, dst;
    if (e < E0) {
        if (g_is64) {
            const long long* p = (const long long*)ei_raw;
            src = (int)p[e];
            dst = (int)p[E0 + e];
        } else {
            const int* p = (const int*)ei_raw;
            src = p[e];
            dst = p[E0 + e];
        }
    } else {
        src = dst = e - E0;
    }
    g_src[e] = src;
    g_dst[e] = dst;
    atomicAdd(&g_deg[dst], 1);
}

__global__ void decode_batch(const void* __restrict__ b_raw) {
    __shared__ int hist[NUM_GRAPHS];
    for (int i = threadIdx.x; i < NUM_GRAPHS; i += blockDim.x) hist[i] = 0;
    __syncthreads();
    int n = blockIdx.x * blockDim.x + threadIdx.x;
    if (n < N_NODES) {
        int b = g_is64 ? (int)((const long long*)b_raw)[n] : ((const int*)b_raw)[n];
        g_batch[n] = b;
        atomicAdd(&hist[b], 1);
    }
    __syncthreads();
    for (int i = threadIdx.x; i < NUM_GRAPHS; i += blockDim.x)
        if (hist[i]) atomicAdd(&g_cnt[i], (float)hist[i]);
}

__global__ void scan_kernel() {
    __shared__ int part[1024];
    int t = threadIdx.x;
    const int CH = (N_NODES + 1023) / 1024;
    int lo = t * CH, hi = min(lo + CH, N_NODES);
    int s = 0;
    for (int i = lo; i < hi; i++) s += g_deg[i];
    part[t] = s;
    __syncthreads();
    for (int o = 1; o < 1024; o <<= 1) {
        int v = (t >= o) ? part[t - o] : 0;
        __syncthreads();
        part[t] += v;
        __syncthreads();
    }
    int base = (t > 0) ? part[t - 1] : 0;
    for (int i = lo; i < hi; i++) {
        g_off[i] = base;
        g_cur[i] = base;
        base += g_deg[i];
    }
    if (t == 1023) g_off[N_NODES] = part[1023];
}

__global__ void scatter_kernel(int Etot) {
    int e = blockIdx.x * blockDim.x + threadIdx.x;
    if (e >= Etot) return;
    int pos = atomicAdd(&g_cur[g_dst[e]], 1);
    g_csr_src[pos] = g_src[e];
}

// ---------------- R4-proven SGEMM: 8x4 microtile, float4 everywhere ----------
// C[M,N] = A[M,K] @ B[K,N], row-major. TBM*TBN == 8192 (256 threads * 32 outputs).
template <int TBM, int TBN>
__global__ void __launch_bounds__(256) sgemm_kernel(const float* __restrict__ A,
                                                    const float* __restrict__ B,
                                                    float* __restrict__ C,
                                                    int M, int N, int K) {
    const int TBK = 32;
    __shared__ float As[TBK][TBM + 4];  // transposed A tile, padded
    __shared__ float Bs[TBK][TBN + 4];

    int tid = threadIdx.x;
    int row0 = blockIdx.y * TBM;
    int col0 = blockIdx.x * TBN;
    int tx = tid % (TBN / 4);   // output col group (4 cols)
    int ty = tid / (TBN / 4);   // output row group (8 rows)

    float acc[8][4];
#pragma unroll
    for (int i = 0; i < 8; i++)
#pragma unroll
        for (int j = 0; j < 4; j++) acc[i][j] = 0.0f;

    const int A_F4 = TBM * TBK / 4;
    const int B_F4 = TBK * TBN / 4;

    for (int k0 = 0; k0 < K; k0 += TBK) {
#pragma unroll
        for (int it = 0; it < A_F4 / 256; it++) {
            int idA = tid + it * 256;
            int kc = idA % (TBK / 4);
            int r = idA / (TBK / 4);
            int gr = row0 + r;
            float4 v = (gr < M) ? *(const float4*)&A[(size_t)gr * K + k0 + kc * 4]
                                : make_float4(0.f, 0.f, 0.f, 0.f);
            As[kc * 4 + 0][r] = v.x;
            As[kc * 4 + 1][r] = v.y;
            As[kc * 4 + 2][r] = v.z;
            As[kc * 4 + 3][r] = v.w;
        }
#pragma unroll
        for (int it = 0; it < B_F4 / 256; it++) {
            int idB = tid + it * 256;
            int c4 = idB % (TBN / 4);
            int r = idB / (TBN / 4);
            *(float4*)&Bs[r][c4 * 4] = *(const float4*)&B[(size_t)(k0 + r) * N + col0 + c4 * 4];
        }
        __syncthreads();

#pragma unroll
        for (int k = 0; k < TBK; k++) {
            float4 a0 = *(const float4*)&As[k][ty * 8];
            float4 a1 = *(const float4*)&As[k][ty * 8 + 4];
            float4 b = *(const float4*)&Bs[k][tx * 4];
            float av[8] = {a0.x, a0.y, a0.z, a0.w, a1.x, a1.y, a1.z, a1.w};
            float bv[4] = {b.x, b.y, b.z, b.w};
#pragma unroll
            for (int i = 0; i < 8; i++)
#pragma unroll
                for (int j = 0; j < 4; j++) acc[i][j] += av[i] * bv[j];
        }
        __syncthreads();
    }

#pragma unroll
    for (int i = 0; i < 8; i++) {
        int gr = row0 + ty * 8 + i;
        if (gr < M) {
            float4 v = make_float4(acc[i][0], acc[i][1], acc[i][2], acc[i][3]);
            *(float4*)&C[(size_t)gr * N + col0 + tx * 4] = v;
        }
    }
}

// ---------------- attention scalars ----------------
__global__ void attn1_kernel(const float* __restrict__ a_src, const float* __restrict__ a_dst) {
    int idx = blockIdx.x * blockDim.x + threadIdx.x;
    if (idx >= N_NODES * H1) return;
    int n = idx >> 2, h = idx & 3;
    const float* hp = &g_h1[(size_t)n * F1 + h * C1];
    const float* ws = &a_src[h * C1];
    const float* wd = &a_dst[h * C1];
    float ss = 0.0f, sd = 0.0f;
#pragma unroll
    for (int j = 0; j < C1; j++) {
        float v = hp[j];
        ss += v * ws[j];
        sd += v * wd[j];
    }
    g_asrc1[idx] = ss;
    g_adst1[idx] = sd;
}

__global__ void attn2_kernel(const float* __restrict__ a_src, const float* __restrict__ a_dst) {
    int w = (blockIdx.x * blockDim.x + threadIdx.x) >> 5;
    int lane = threadIdx.x & 31;
    if (w >= N_NODES) return;
    const float* hp = &g_h2[(size_t)w * C2];
    float ss = 0.0f, sd = 0.0f;
#pragma unroll
    for (int k = 0; k < 3; k++) {
        int j = lane + 32 * k;
        float v = hp[j];
        ss += v * a_src[j];
        sd += v * a_dst[j];
    }
#pragma unroll
    for (int o = 16; o > 0; o >>= 1) {
        ss += __shfl_down_sync(0xffffffffu, ss, o);
        sd += __shfl_down_sync(0xffffffffu, sd, o);
    }
    if (lane == 0) {
        g_asrc2[w] = ss;
        g_adst2[w] = sd;
    }
}

// ---------------- layer 1 fused: softmax + aggregate + bias + relu (warp/node) ----
// lane owns channels [lane*4, lane*4+4) and [128+lane*2, 128+lane*2+2)
__global__ void gat1_kernel(const float* __restrict__ b1) {
    int node = (blockIdx.x * blockDim.x + threadIdx.x) >> 5;
    int lane = threadIdx.x & 31;
    if (node >= N_NODES) return;
    int start = g_off[node], end = g_off[node + 1];

    float4 ad = *(const float4*)&g_adst1[node * H1];

    float4 den = make_float4(0.f, 0.f, 0.f, 0.f);
    for (int idx = start + lane; idx < end; idx += 32) {
        int src = g_csr_src[idx];
        float4 as = *(const float4*)&g_asrc1[src * H1];
        float4 p;
        p.x = __expf(leaky(as.x + ad.x));
        p.y = __expf(leaky(as.y + ad.y));
        p.z = __expf(leaky(as.z + ad.z));
        p.w = __expf(leaky(as.w + ad.w));
        *(float4*)&g_p[(size_t)idx * 4] = p;
        den.x += p.x; den.y += p.y; den.z += p.z; den.w += p.w;
    }
#pragma unroll
    for (int o = 16; o > 0; o >>= 1) {
        den.x += __shfl_xor_sync(0xffffffffu, den.x, o);
        den.y += __shfl_xor_sync(0xffffffffu, den.y, o);
        den.z += __shfl_xor_sync(0xffffffffu, den.z, o);
        den.w += __shfl_xor_sync(0xffffffffu, den.w, o);
    }
    float inv0 = 1.0f / den.x, inv1 = 1.0f / den.y, inv2 = 1.0f / den.z, inv3 = 1.0f / den.w;

    int c4 = lane * 4;
    int c2 = 128 + lane * 2;
    int hA = c4 / C1;                                  // {0,1,2}
    int hB = c2 / C1;                                  // {2,3}
    float invA = (hA == 0) ? inv0 : (hA == 1) ? inv1 : inv2;
    float invB = (hB == 2) ? inv2 : inv3;

    float4 acc4 = make_float4(0.f, 0.f, 0.f, 0.f);
    float2 acc2 = make_float2(0.f, 0.f);
#pragma unroll 2
    for (int idx = start; idx < end; idx++) {
        int src = g_csr_src[idx];
        float4 p4 = *(const float4*)&g_p[(size_t)idx * 4];
        float pA = (hA == 0) ? p4.x : (hA == 1) ? p4.y : p4.z;
        float pB = (hB == 2) ? p4.z : p4.w;
        float alA = pA * invA;
        float alB = pB * invB;
        const float* hp = &g_h1[(size_t)src * F1];
        float4 hv4 = *(const float4*)&hp[c4];
        float2 hv2 = *(const float2*)&hp[c2];
        acc4.x += hv4.x * alA; acc4.y += hv4.y * alA;
        acc4.z += hv4.z * alA; acc4.w += hv4.w * alA;
        acc2.x += hv2.x * alB; acc2.y += hv2.y * alB;
    }
    float4 bb4 = *(const float4*)&b1[c4];
    float2 bb2 = *(const float2*)&b1[c2];
    float4 o4 = make_float4(fmaxf(acc4.x + bb4.x, 0.f), fmaxf(acc4.y + bb4.y, 0.f),
                            fmaxf(acc4.z + bb4.z, 0.f), fmaxf(acc4.w + bb4.w, 0.f));
    float2 o2 = make_float2(fmaxf(acc2.x + bb2.x, 0.f), fmaxf(acc2.y + bb2.y, 0.f));
    *(float4*)&g_h1r[(size_t)node * F1 + c4] = o4;
    *(float2*)&g_h1r[(size_t)node * F1 + c2] = o2;
}

// ---------------- layer 2 fused: softmax + aggregate + bias + relu + pool ----
__global__ void gat2_kernel(const float* __restrict__ b2) {
    int node = (blockIdx.x * blockDim.x + threadIdx.x) >> 5;
    int lane = threadIdx.x & 31;
    if (node >= N_NODES) return;
    int start = g_off[node], end = g_off[node + 1];

    float ad = g_adst2[node];
    float den = 0.0f;
    for (int idx = start + lane; idx < end; idx += 32) {
        int src = g_csr_src[idx];
        float p = __expf(leaky(g_asrc2[src] + ad));
        g_p[idx] = p;
        den += p;
    }
#pragma unroll
    for (int o = 16; o > 0; o >>= 1) den += __shfl_xor_sync(0xffffffffu, den, o);
    float inv = 1.0f / den;

    int c2 = lane * 2;
    int cs = 64 + lane;
    float2 acc2 = make_float2(0.f, 0.f);
    float accs = 0.0f;
#pragma unroll 2
    for (int idx = start; idx < end; idx++) {
        int src = g_csr_src[idx];
        float alpha = g_p[idx] * inv;
        const float* hp = &g_h2[(size_t)src * C2];
        float2 hv2 = *(const float2*)&hp[c2];
        float hvs = hp[cs];
        acc2.x += hv2.x * alpha;
        acc2.y += hv2.y * alpha;
        accs += hvs * alpha;
    }
    int gp = g_batch[node] * C2;
    atomicAdd(&g_pool[gp + c2], fmaxf(acc2.x + b2[c2], 0.0f));
    atomicAdd(&g_pool[gp + c2 + 1], fmaxf(acc2.y + b2[c2 + 1], 0.0f));
    atomicAdd(&g_pool[gp + cs], fmaxf(accs + b2[cs], 0.0f));
}

// ---------------- final MLP: one block per graph ----------------
__global__ void mlp_kernel(const float* __restrict__ fc1_w, const float* __restrict__ fc1_b,
                           const float* __restrict__ fc2_w, const float* __restrict__ fc2_b,
                           float* __restrict__ out) {
    __shared__ float p[C2];
    __shared__ float z[192];
    int g = blockIdx.x;
    int t = threadIdx.x;
    float inv = 1.0f / fmaxf(g_cnt[g], 1.0f);
    if (t < C2) p[t] = g_pool[g * C2 + t] * inv;
    __syncthreads();
    float acc = fc1_b[t];
#pragma unroll
    for (int k = 0; k < C2; k++) acc += p[k] * fc1_w[k * 192 + t];
    z[t] = fmaxf(acc, 0.0f);
    __syncthreads();
    if (t < C2) {
        float o = fc2_b[t];
#pragma unroll
        for (int k = 0; k < 192; k++) o += z[k] * fc2_w[k * C2 + t];
        out[g * C2 + t] = o;
    }
}

// ---------------- host launch ----------------
extern "C" void kernel_launch(void* const* d_in, const int* in_sizes, int n_in,
                              void* d_out, int out_size) {
    const float* x = (const float*)d_in[0];
    const void* ei_raw = d_in[1];
    const void* batch_raw = d_in[2];
    const float* W1 = (const float*)d_in[3];
    const float* a_src1 = (const float*)d_in[4];
    const float* a_dst1 = (const float*)d_in[5];
    const float* b1 = (const float*)d_in[6];
    const float* W2 = (const float*)d_in[7];
    const float* a_src2 = (const float*)d_in[8];
    const float* a_dst2 = (const float*)d_in[9];
    const float* b2 = (const float*)d_in[10];
    const float* fc1_w = (const float*)d_in[11];
    const float* fc1_b = (const float*)d_in[12];
    const float* fc2_w = (const float*)d_in[13];
    const float* fc2_b = (const float*)d_in[14];
    float* out = (float*)d_out;

    int E0 = in_sizes[1] / 2;
    int Etot = E0 + N_NODES;

    float *h1p, *h1rp, *h2p;
    cudaGetSymbolAddress((void**)&h1p, g_h1);
    cudaGetSymbolAddress((void**)&h1rp, g_h1r);
    cudaGetSymbolAddress((void**)&h2p, g_h2);

    // graph preprocessing
    init_kernel<<<256, 256>>>();
    sniff_kernel<<<1, 256>>>((const unsigned int*)ei_raw);
    decode_edges<<<(Etot + 255) / 256, 256>>>(ei_raw, E0);
    decode_batch<<<(N_NODES + 255) / 256, 256>>>(batch_raw);
    scan_kernel<<<1, 1024>>>();
    scatter_kernel<<<(Etot + 255) / 256, 256>>>(Etot);

    // layer 1 GEMM: [100000,128] @ [128,192]
    {
        dim3 grid(F1 / 64, (N_NODES + 127) / 128);
        sgemm_kernel<128, 64><<<grid, 256>>>(x, W1, h1p, N_NODES, F1, D_IN);
    }
    attn1_kernel<<<(N_NODES * H1 + 255) / 256, 256>>>(a_src1, a_dst1);
    gat1_kernel<<<(N_NODES + 7) / 8, 256>>>(b1);

    // layer 2 GEMM: [100000,192] @ [192,96]
    {
        dim3 grid(C2 / 32, (N_NODES + 255) / 256);
        sgemm_kernel<256, 32><<<grid, 256>>>(h1rp, W2, h2p, N_NODES, C2, F1);
    }
    attn2_kernel<<<(N_NODES * 32 + 255) / 256, 256>>>(a_src2, a_dst2);
    gat2_kernel<<<(N_NODES + 7) / 8, 256>>>(b2);

    // MLP head
    mlp_kernel<<<NUM_GRAPHS, 192>>>(fc1_w, fc1_b, fc2_w, fc2_b, out);
}

// round 8
// speedup vs baseline: 1.2774x; 1.0936x over previous
#include <cuda_runtime.h>
#include <math.h>

#define N_NODES 100000
#define NUM_GRAPHS 128
#define H1 4
#define C1 48
#define F1 192   // H1*C1
#define C2 96
#define D_IN 128
#define NEG_SLOPE 0.2f
#define E_MAX 1750000   // raw edges (1.6M) + self loops (100k) with slack

// ---------------- scratch (device globals; no allocation) ----------------
__device__ float g_h1[N_NODES * F1];      // x @ W1
__device__ float g_h1r[N_NODES * F1];     // layer1 output (relu'd)
__device__ float g_asrc1[N_NODES * H1];
__device__ float g_adst1[N_NODES * H1];
__device__ float g_h2[N_NODES * C2];      // h1r @ W2
__device__ float g_asrc2[N_NODES];
__device__ float g_adst2[N_NODES];
__device__ float g_pool[NUM_GRAPHS * C2];
__device__ float g_cnt[NUM_GRAPHS];
__device__ int g_src[E_MAX];
__device__ int g_dst[E_MAX];
__device__ int g_batch[N_NODES];
__device__ int g_is64;
__device__ int g_deg[N_NODES];
__device__ int g_off[N_NODES + 1];
__device__ int g_cur[N_NODES];
__device__ int g_csr_src[E_MAX];
__device__ float g_p[E_MAX * H1];

__device__ __forceinline__ float leaky(float s) {
    return s > 0.0f ? s : NEG_SLOPE * s;
}

// ---------------- init (zero counters only) ----------------
__global__ void init_kernel() {
    int i = blockIdx.x * blockDim.x + threadIdx.x;
    int stride = gridDim.x * blockDim.x;
    for (int k = i; k < N_NODES; k += stride) g_deg[k] = 0;
    for (int k = i; k < NUM_GRAPHS * C2; k += stride) g_pool[k] = 0.0f;
    for (int k = i; k < NUM_GRAPHS; k += stride) g_cnt[k] = 0.0f;
}

// ---------------- dtype sniff: int64 vs int32 index buffers ----------------
__global__ void sniff_kernel(const unsigned int* __restrict__ w) {
    __shared__ int any_nonzero;
    if (threadIdx.x == 0) any_nonzero = 0;
    __syncthreads();
    for (int i = threadIdx.x; i < 256; i += blockDim.x) {
        if (w[2 * i + 1] != 0u) any_nonzero = 1;
    }
    __syncthreads();
    if (threadIdx.x == 0) g_is64 = (any_nonzero == 0) ? 1 : 0;
}

__global__ void decode_edges(const void* __restrict__ ei_raw, int E0) {
    int e = blockIdx.x * blockDim.x + threadIdx.x;
    int Etot = E0 + N_NODES;
    if (e >= Etot) return;
    int src, dst;
    if (e < E0) {
        if (g_is64) {
            const long long* p = (const long long*)ei_raw;
            src = (int)p[e];
            dst = (int)p[E0 + e];
        } else {
            const int* p = (const int*)ei_raw;
            src = p[e];
            dst = p[E0 + e];
        }
    } else {
        src = dst = e - E0;
    }
    g_src[e] = src;
    g_dst[e] = dst;
    atomicAdd(&g_deg[dst], 1);
}

__global__ void decode_batch(const void* __restrict__ b_raw) {
    __shared__ int hist[NUM_GRAPHS];
    for (int i = threadIdx.x; i < NUM_GRAPHS; i += blockDim.x) hist[i] = 0;
    __syncthreads();
    int n = blockIdx.x * blockDim.x + threadIdx.x;
    if (n < N_NODES) {
        int b = g_is64 ? (int)((const long long*)b_raw)[n] : ((const int*)b_raw)[n];
        g_batch[n] = b;
        atomicAdd(&hist[b], 1);
    }
    __syncthreads();
    for (int i = threadIdx.x; i < NUM_GRAPHS; i += blockDim.x)
        if (hist[i]) atomicAdd(&g_cnt[i], (float)hist[i]);
}

__global__ void scan_kernel() {
    __shared__ int part[1024];
    int t = threadIdx.x;
    const int CH = (N_NODES + 1023) / 1024;
    int lo = t * CH, hi = min(lo + CH, N_NODES);
    int s = 0;
    for (int i = lo; i < hi; i++) s += g_deg[i];
    part[t] = s;
    __syncthreads();
    for (int o = 1; o < 1024; o <<= 1) {
        int v = (t >= o) ? part[t - o] : 0;
        __syncthreads();
        part[t] += v;
        __syncthreads();
    }
    int base = (t > 0) ? part[t - 1] : 0;
    for (int i = lo; i < hi; i++) {
        g_off[i] = base;
        g_cur[i] = base;
        base += g_deg[i];
    }
    if (t == 1023) g_off[N_NODES] = part[1023];
}

__global__ void scatter_kernel(int Etot) {
    int e = blockIdx.x * blockDim.x + threadIdx.x;
    if (e >= Etot) return;
    int pos = atomicAdd(&g_cur[g_dst[e]], 1);
    g_csr_src[pos] = g_src[e];
}

// ---------------- R4-proven SGEMM: 8x4 microtile, float4 everywhere ----------
template <int TBM, int TBN>
__global__ void __launch_bounds__(256) sgemm_kernel(const float* __restrict__ A,
                                                    const float* __restrict__ B,
                                                    float* __restrict__ C,
                                                    int M, int N, int K) {
    const int TBK = 32;
    __shared__ float As[TBK][TBM + 4];
    __shared__ float Bs[TBK][TBN + 4];

    int tid = threadIdx.x;
    int row0 = blockIdx.y * TBM;
    int col0 = blockIdx.x * TBN;
    int tx = tid % (TBN / 4);
    int ty = tid / (TBN / 4);

    float acc[8][4];
#pragma unroll
    for (int i = 0; i < 8; i++)
#pragma unroll
        for (int j = 0; j < 4; j++) acc[i][j] = 0.0f;

    const int A_F4 = TBM * TBK / 4;
    const int B_F4 = TBK * TBN / 4;

    for (int k0 = 0; k0 < K; k0 += TBK) {
#pragma unroll
        for (int it = 0; it < A_F4 / 256; it++) {
            int idA = tid + it * 256;
            int kc = idA % (TBK / 4);
            int r = idA / (TBK / 4);
            int gr = row0 + r;
            float4 v = (gr < M) ? *(const float4*)&A[(size_t)gr * K + k0 + kc * 4]
                                : make_float4(0.f, 0.f, 0.f, 0.f);
            As[kc * 4 + 0][r] = v.x;
            As[kc * 4 + 1][r] = v.y;
            As[kc * 4 + 2][r] = v.z;
            As[kc * 4 + 3][r] = v.w;
        }
#pragma unroll
        for (int it = 0; it < B_F4 / 256; it++) {
            int idB = tid + it * 256;
            int c4 = idB % (TBN / 4);
            int r = idB / (TBN / 4);
            *(float4*)&Bs[r][c4 * 4] = *(const float4*)&B[(size_t)(k0 + r) * N + col0 + c4 * 4];
        }
        __syncthreads();

#pragma unroll
        for (int k = 0; k < TBK; k++) {
            float4 a0 = *(const float4*)&As[k][ty * 8];
            float4 a1 = *(const float4*)&As[k][ty * 8 + 4];
            float4 b = *(const float4*)&Bs[k][tx * 4];
            float av[8] = {a0.x, a0.y, a0.z, a0.w, a1.x, a1.y, a1.z, a1.w};
            float bv[4] = {b.x, b.y, b.z, b.w};
#pragma unroll
            for (int i = 0; i < 8; i++)
#pragma unroll
                for (int j = 0; j < 4; j++) acc[i][j] += av[i] * bv[j];
        }
        __syncthreads();
    }

#pragma unroll
    for (int i = 0; i < 8; i++) {
        int gr = row0 + ty * 8 + i;
        if (gr < M) {
            float4 v = make_float4(acc[i][0], acc[i][1], acc[i][2], acc[i][3]);
            *(float4*)&C[(size_t)gr * N + col0 + tx * 4] = v;
        }
    }
}

// ---------------- attention scalars ----------------
__global__ void attn1_kernel(const float* __restrict__ a_src, const float* __restrict__ a_dst) {
    int idx = blockIdx.x * blockDim.x + threadIdx.x;
    if (idx >= N_NODES * H1) return;
    int n = idx >> 2, h = idx & 3;
    const float* hp = &g_h1[(size_t)n * F1 + h * C1];
    const float* ws = &a_src[h * C1];
    const float* wd = &a_dst[h * C1];
    float ss = 0.0f, sd = 0.0f;
#pragma unroll
    for (int j = 0; j < C1; j++) {
        float v = hp[j];
        ss += v * ws[j];
        sd += v * wd[j];
    }
    g_asrc1[idx] = ss;
    g_adst1[idx] = sd;
}

__global__ void attn2_kernel(const float* __restrict__ a_src, const float* __restrict__ a_dst) {
    int w = (blockIdx.x * blockDim.x + threadIdx.x) >> 5;
    int lane = threadIdx.x & 31;
    if (w >= N_NODES) return;
    const float* hp = &g_h2[(size_t)w * C2];
    float ss = 0.0f, sd = 0.0f;
#pragma unroll
    for (int k = 0; k < 3; k++) {
        int j = lane + 32 * k;
        float v = hp[j];
        ss += v * a_src[j];
        sd += v * a_dst[j];
    }
#pragma unroll
    for (int o = 16; o > 0; o >>= 1) {
        ss += __shfl_down_sync(0xffffffffu, ss, o);
        sd += __shfl_down_sync(0xffffffffu, sd, o);
    }
    if (lane == 0) {
        g_asrc2[w] = ss;
        g_adst2[w] = sd;
    }
}

// ---------------- layer 1 fused (R4-proven scalar gathers) ----------------
__global__ void gat1_kernel(const float* __restrict__ b1) {
    int node = (blockIdx.x * blockDim.x + threadIdx.x) >> 5;
    int lane = threadIdx.x & 31;
    if (node >= N_NODES) return;
    int start = g_off[node], end = g_off[node + 1];

    float4 ad = *(const float4*)&g_adst1[node * H1];

    float4 den = make_float4(0.f, 0.f, 0.f, 0.f);
    for (int idx = start + lane; idx < end; idx += 32) {
        int src = g_csr_src[idx];
        float4 as = *(const float4*)&g_asrc1[src * H1];
        float4 p;
        p.x = __expf(leaky(as.x + ad.x));
        p.y = __expf(leaky(as.y + ad.y));
        p.z = __expf(leaky(as.z + ad.z));
        p.w = __expf(leaky(as.w + ad.w));
        *(float4*)&g_p[(size_t)idx * 4] = p;
        den.x += p.x; den.y += p.y; den.z += p.z; den.w += p.w;
    }
#pragma unroll
    for (int o = 16; o > 0; o >>= 1) {
        den.x += __shfl_xor_sync(0xffffffffu, den.x, o);
        den.y += __shfl_xor_sync(0xffffffffu, den.y, o);
        den.z += __shfl_xor_sync(0xffffffffu, den.z, o);
        den.w += __shfl_xor_sync(0xffffffffu, den.w, o);
    }
    float inv0 = 1.0f / den.x, inv1 = 1.0f / den.y, inv2 = 1.0f / den.z, inv3 = 1.0f / den.w;

    float acc[6] = {0.f, 0.f, 0.f, 0.f, 0.f, 0.f};
    for (int idx = start; idx < end; idx++) {
        int src = g_csr_src[idx];
        float4 p4 = *(const float4*)&g_p[(size_t)idx * 4];
        float a0 = p4.x * inv0, a1 = p4.y * inv1, a2 = p4.z * inv2, a3 = p4.w * inv3;
        const float* hp = &g_h1[(size_t)src * F1];
#pragma unroll
        for (int k = 0; k < 6; k++) {
            int c = k * 32 + lane;
            float al = (c < 48) ? a0 : (c < 96) ? a1 : (c < 144) ? a2 : a3;
            acc[k] += hp[c] * al;
        }
    }
#pragma unroll
    for (int k = 0; k < 6; k++) {
        int c = k * 32 + lane;
        g_h1r[(size_t)node * F1 + c] = fmaxf(acc[k] + b1[c], 0.0f);
    }
}

// ---------------- layer 2 fused (R4-proven scalar gathers) ----------------
__global__ void gat2_kernel(const float* __restrict__ b2) {
    int node = (blockIdx.x * blockDim.x + threadIdx.x) >> 5;
    int lane = threadIdx.x & 31;
    if (node >= N_NODES) return;
    int start = g_off[node], end = g_off[node + 1];

    float ad = g_adst2[node];
    float den = 0.0f;
    for (int idx = start + lane; idx < end; idx += 32) {
        int src = g_csr_src[idx];
        float p = __expf(leaky(g_asrc2[src] + ad));
        g_p[idx] = p;
        den += p;
    }
#pragma unroll
    for (int o = 16; o > 0; o >>= 1) den += __shfl_xor_sync(0xffffffffu, den, o);
    float inv = 1.0f / den;

    float acc[3] = {0.f, 0.f, 0.f};
    for (int idx = start; idx < end; idx++) {
        int src = g_csr_src[idx];
        float alpha = g_p[idx] * inv;
        const float* hp = &g_h2[(size_t)src * C2];
#pragma unroll
        for (int k = 0; k < 3; k++) acc[k] += hp[k * 32 + lane] * alpha;
    }
    int gp = g_batch[node] * C2;
#pragma unroll
    for (int k = 0; k < 3; k++) {
        int c = k * 32 + lane;
        float v = fmaxf(acc[k] + b2[c], 0.0f);
        atomicAdd(&g_pool[gp + c], v);
    }
}

// ---------------- final MLP: one block per graph ----------------
__global__ void mlp_kernel(const float* __restrict__ fc1_w, const float* __restrict__ fc1_b,
                           const float* __restrict__ fc2_w, const float* __restrict__ fc2_b,
                           float* __restrict__ out) {
    __shared__ float p[C2];
    __shared__ float z[192];
    int g = blockIdx.x;
    int t = threadIdx.x;
    float inv = 1.0f / fmaxf(g_cnt[g], 1.0f);
    if (t < C2) p[t] = g_pool[g * C2 + t] * inv;
    __syncthreads();
    float acc = fc1_b[t];
#pragma unroll
    for (int k = 0; k < C2; k++) acc += p[k] * fc1_w[k * 192 + t];
    z[t] = fmaxf(acc, 0.0f);
    __syncthreads();
    if (t < C2) {
        float o = fc2_b[t];
#pragma unroll
        for (int k = 0; k < 192; k++) o += z[k] * fc2_w[k * C2 + t];
        out[g * C2 + t] = o;
    }
}

// ---------------- host launch (two-stream overlap, capture-legal) ----------
extern "C" void kernel_launch(void* const* d_in, const int* in_sizes, int n_in,
                              void* d_out, int out_size) {
    const float* x = (const float*)d_in[0];
    const void* ei_raw = d_in[1];
    const void* batch_raw = d_in[2];
    const float* W1 = (const float*)d_in[3];
    const float* a_src1 = (const float*)d_in[4];
    const float* a_dst1 = (const float*)d_in[5];
    const float* b1 = (const float*)d_in[6];
    const float* W2 = (const float*)d_in[7];
    const float* a_src2 = (const float*)d_in[8];
    const float* a_dst2 = (const float*)d_in[9];
    const float* b2 = (const float*)d_in[10];
    const float* fc1_w = (const float*)d_in[11];
    const float* fc1_b = (const float*)d_in[12];
    const float* fc2_w = (const float*)d_in[13];
    const float* fc2_b = (const float*)d_in[14];
    float* out = (float*)d_out;

    int E0 = in_sizes[1] / 2;
    int Etot = E0 + N_NODES;

    float *h1p, *h1rp, *h2p;
    cudaGetSymbolAddress((void**)&h1p, g_h1);
    cudaGetSymbolAddress((void**)&h1rp, g_h1r);
    cudaGetSymbolAddress((void**)&h2p, g_h2);

    // fork a side stream for graph preprocessing (host-side resources only;
    // created fresh per call — a handful of calls total, no device memory)
    cudaStream_t sB;
    cudaStreamCreateWithFlags(&sB, cudaStreamNonBlocking);
    cudaEvent_t evFork, evJoin;
    cudaEventCreateWithFlags(&evFork, cudaEventDisableTiming);
    cudaEventCreateWithFlags(&evJoin, cudaEventDisableTiming);

    cudaEventRecord(evFork, 0);
    cudaStreamWaitEvent(sB, evFork, 0);

    // ---- stream B: CSR build + batch decode ----
    init_kernel<<<256, 256, 0, sB>>>();
    sniff_kernel<<<1, 256, 0, sB>>>((const unsigned int*)ei_raw);
    decode_edges<<<(Etot + 255) / 256, 256, 0, sB>>>(ei_raw, E0);
    decode_batch<<<(N_NODES + 255) / 256, 256, 0, sB>>>(batch_raw);
    scan_kernel<<<1, 1024, 0, sB>>>();
    scatter_kernel<<<(Etot + 255) / 256, 256, 0, sB>>>(Etot);
    cudaEventRecord(evJoin, sB);

    // ---- default stream: GEMM1 + attn1 (independent of CSR) ----
    {
        dim3 grid(F1 / 64, (N_NODES + 127) / 128);
        sgemm_kernel<128, 64><<<grid, 256>>>(x, W1, h1p, N_NODES, F1, D_IN);
    }
    attn1_kernel<<<(N_NODES * H1 + 255) / 256, 256>>>(a_src1, a_dst1);

    // join: gat1 needs both chains
    cudaStreamWaitEvent(0, evJoin, 0);

    gat1_kernel<<<(N_NODES + 7) / 8, 256>>>(b1);

    // layer 2
    {
        dim3 grid(C2 / 32, (N_NODES + 255) / 256);
        sgemm_kernel<256, 32><<<grid, 256>>>(h1rp, W2, h2p, N_NODES, C2, F1);
    }
    attn2_kernel<<<(N_NODES * 32 + 255) / 256, 256>>>(a_src2, a_dst2);
    gat2_kernel<<<(N_NODES + 7) / 8, 256>>>(b2);

    // MLP head
    mlp_kernel<<<NUM_GRAPHS, 192>>>(fc1_w, fc1_b, fc2_w, fc2_b, out);
}

// round 9
// speedup vs baseline: 1.3262x; 1.0382x over previous
#include <cuda_runtime.h>
#include <cuda_fp16.h>
#include <math.h>

#define N_NODES 100000
#define NUM_GRAPHS 128
#define H1 4
#define C1 48
#define F1 192   // H1*C1
#define C2 96
#define D_IN 128
#define NEG_SLOPE 0.2f
#define E_MAX 1750000   // raw edges (1.6M) + self loops (100k) with slack

// ---------------- scratch (device globals; no allocation) ----------------
__device__ float g_h1[N_NODES * F1];        // x @ W1 (fp32, for attn1)
__device__ __half g_h1h[N_NODES * F1];      // fp16 copy (gather table for gat1)
__device__ float g_h1r[N_NODES * F1];       // layer1 output (relu'd)
__device__ float g_asrc1[N_NODES * H1];
__device__ float g_adst1[N_NODES * H1];
__device__ float g_h2[N_NODES * C2];        // h1r @ W2 (fp32, for attn2)
__device__ __half g_h2h[N_NODES * C2];      // fp16 copy (gather table for gat2)
__device__ float g_asrc2[N_NODES];
__device__ float g_adst2[N_NODES];
__device__ float g_pool[NUM_GRAPHS * C2];
__device__ float g_cnt[NUM_GRAPHS];
__device__ int g_src[E_MAX];
__device__ int g_dst[E_MAX];
__device__ int g_batch[N_NODES];
__device__ int g_is64;
__device__ int g_deg[N_NODES];
__device__ int g_off[N_NODES + 1];
__device__ int g_cur[N_NODES];
__device__ int g_csr_src[E_MAX];
__device__ float g_p[E_MAX * H1];

__device__ __forceinline__ float leaky(float s) {
    return s > 0.0f ? s : NEG_SLOPE * s;
}

// ---------------- init (zero counters only) ----------------
__global__ void init_kernel() {
    int i = blockIdx.x * blockDim.x + threadIdx.x;
    int stride = gridDim.x * blockDim.x;
    for (int k = i; k < N_NODES; k += stride) g_deg[k] = 0;
    for (int k = i; k < NUM_GRAPHS * C2; k += stride) g_pool[k] = 0.0f;
    for (int k = i; k < NUM_GRAPHS; k += stride) g_cnt[k] = 0.0f;
}

// ---------------- dtype sniff: int64 vs int32 index buffers ----------------
__global__ void sniff_kernel(const unsigned int* __restrict__ w) {
    __shared__ int any_nonzero;
    if (threadIdx.x == 0) any_nonzero = 0;
    __syncthreads();
    for (int i = threadIdx.x; i < 256; i += blockDim.x) {
        if (w[2 * i + 1] != 0u) any_nonzero = 1;
    }
    __syncthreads();
    if (threadIdx.x == 0) g_is64 = (any_nonzero == 0) ? 1 : 0;
}

__global__ void decode_edges(const void* __restrict__ ei_raw, int E0) {
    int e = blockIdx.x * blockDim.x + threadIdx.x;
    int Etot = E0 + N_NODES;
    if (e >= Etot) return;
    int src, dst;
    if (e < E0) {
        if (g_is64) {
            const long long* p = (const long long*)ei_raw;
            src = (int)p[e];
            dst = (int)p[E0 + e];
        } else {
            const int* p = (const int*)ei_raw;
            src = p[e];
            dst = p[E0 + e];
        }
    } else {
        src = dst = e - E0;
    }
    g_src[e] = src;
    g_dst[e] = dst;
    atomicAdd(&g_deg[dst], 1);
}

__global__ void decode_batch(const void* __restrict__ b_raw) {
    __shared__ int hist[NUM_GRAPHS];
    for (int i = threadIdx.x; i < NUM_GRAPHS; i += blockDim.x) hist[i] = 0;
    __syncthreads();
    int n = blockIdx.x * blockDim.x + threadIdx.x;
    if (n < N_NODES) {
        int b = g_is64 ? (int)((const long long*)b_raw)[n] : ((const int*)b_raw)[n];
        g_batch[n] = b;
        atomicAdd(&hist[b], 1);
    }
    __syncthreads();
    for (int i = threadIdx.x; i < NUM_GRAPHS; i += blockDim.x)
        if (hist[i]) atomicAdd(&g_cnt[i], (float)hist[i]);
}

__global__ void scan_kernel() {
    __shared__ int part[1024];
    int t = threadIdx.x;
    const int CH = (N_NODES + 1023) / 1024;
    int lo = t * CH, hi = min(lo + CH, N_NODES);
    int s = 0;
    for (int i = lo; i < hi; i++) s += g_deg[i];
    part[t] = s;
    __syncthreads();
    for (int o = 1; o < 1024; o <<= 1) {
        int v = (t >= o) ? part[t - o] : 0;
        __syncthreads();
        part[t] += v;
        __syncthreads();
    }
    int base = (t > 0) ? part[t - 1] : 0;
    for (int i = lo; i < hi; i++) {
        g_off[i] = base;
        g_cur[i] = base;
        base += g_deg[i];
    }
    if (t == 1023) g_off[N_NODES] = part[1023];
}

__global__ void scatter_kernel(int Etot) {
    int e = blockIdx.x * blockDim.x + threadIdx.x;
    if (e >= Etot) return;
    int pos = atomicAdd(&g_cur[g_dst[e]], 1);
    g_csr_src[pos] = g_src[e];
}

// ---------------- R4-proven SGEMM + optional fp16 shadow copy ---------------
template <int TBM, int TBN, bool WRITE_HALF>
__global__ void __launch_bounds__(256) sgemm_kernel(const float* __restrict__ A,
                                                    const float* __restrict__ B,
                                                    float* __restrict__ C,
                                                    __half* __restrict__ Ch,
                                                    int M, int N, int K) {
    const int TBK = 32;
    __shared__ float As[TBK][TBM + 4];
    __shared__ float Bs[TBK][TBN + 4];

    int tid = threadIdx.x;
    int row0 = blockIdx.y * TBM;
    int col0 = blockIdx.x * TBN;
    int tx = tid % (TBN / 4);
    int ty = tid / (TBN / 4);

    float acc[8][4];
#pragma unroll
    for (int i = 0; i < 8; i++)
#pragma unroll
        for (int j = 0; j < 4; j++) acc[i][j] = 0.0f;

    const int A_F4 = TBM * TBK / 4;
    const int B_F4 = TBK * TBN / 4;

    for (int k0 = 0; k0 < K; k0 += TBK) {
#pragma unroll
        for (int it = 0; it < A_F4 / 256; it++) {
            int idA = tid + it * 256;
            int kc = idA % (TBK / 4);
            int r = idA / (TBK / 4);
            int gr = row0 + r;
            float4 v = (gr < M) ? *(const float4*)&A[(size_t)gr * K + k0 + kc * 4]
                                : make_float4(0.f, 0.f, 0.f, 0.f);
            As[kc * 4 + 0][r] = v.x;
            As[kc * 4 + 1][r] = v.y;
            As[kc * 4 + 2][r] = v.z;
            As[kc * 4 + 3][r] = v.w;
        }
#pragma unroll
        for (int it = 0; it < B_F4 / 256; it++) {
            int idB = tid + it * 256;
            int c4 = idB % (TBN / 4);
            int r = idB / (TBN / 4);
            *(float4*)&Bs[r][c4 * 4] = *(const float4*)&B[(size_t)(k0 + r) * N + col0 + c4 * 4];
        }
        __syncthreads();

#pragma unroll
        for (int k = 0; k < TBK; k++) {
            float4 a0 = *(const float4*)&As[k][ty * 8];
            float4 a1 = *(const float4*)&As[k][ty * 8 + 4];
            float4 b = *(const float4*)&Bs[k][tx * 4];
            float av[8] = {a0.x, a0.y, a0.z, a0.w, a1.x, a1.y, a1.z, a1.w};
            float bv[4] = {b.x, b.y, b.z, b.w};
#pragma unroll
            for (int i = 0; i < 8; i++)
#pragma unroll
                for (int j = 0; j < 4; j++) acc[i][j] += av[i] * bv[j];
        }
        __syncthreads();
    }

#pragma unroll
    for (int i = 0; i < 8; i++) {
        int gr = row0 + ty * 8 + i;
        if (gr < M) {
            float4 v = make_float4(acc[i][0], acc[i][1], acc[i][2], acc[i][3]);
            *(float4*)&C[(size_t)gr * N + col0 + tx * 4] = v;
            if (WRITE_HALF) {
                __half2 h01 = __floats2half2_rn(v.x, v.y);
                __half2 h23 = __floats2half2_rn(v.z, v.w);
                *(__half2*)&Ch[(size_t)gr * N + col0 + tx * 4] = h01;
                *(__half2*)&Ch[(size_t)gr * N + col0 + tx * 4 + 2] = h23;
            }
        }
    }
}

// ---------------- attention scalars ----------------
__global__ void attn1_kernel(const float* __restrict__ a_src, const float* __restrict__ a_dst) {
    int idx = blockIdx.x * blockDim.x + threadIdx.x;
    if (idx >= N_NODES * H1) return;
    int n = idx >> 2, h = idx & 3;
    const float* hp = &g_h1[(size_t)n * F1 + h * C1];
    const float* ws = &a_src[h * C1];
    const float* wd = &a_dst[h * C1];
    float ss = 0.0f, sd = 0.0f;
#pragma unroll
    for (int j = 0; j < C1; j++) {
        float v = hp[j];
        ss += v * ws[j];
        sd += v * wd[j];
    }
    g_asrc1[idx] = ss;
    g_adst1[idx] = sd;
}

__global__ void attn2_kernel(const float* __restrict__ a_src, const float* __restrict__ a_dst) {
    int w = (blockIdx.x * blockDim.x + threadIdx.x) >> 5;
    int lane = threadIdx.x & 31;
    if (w >= N_NODES) return;
    const float* hp = &g_h2[(size_t)w * C2];
    float ss = 0.0f, sd = 0.0f;
#pragma unroll
    for (int k = 0; k < 3; k++) {
        int j = lane + 32 * k;
        float v = hp[j];
        ss += v * a_src[j];
        sd += v * a_dst[j];
    }
#pragma unroll
    for (int o = 16; o > 0; o >>= 1) {
        ss += __shfl_down_sync(0xffffffffu, ss, o);
        sd += __shfl_down_sync(0xffffffffu, sd, o);
    }
    if (lane == 0) {
        g_asrc2[w] = ss;
        g_adst2[w] = sd;
    }
}

// ---------------- layer 1 fused: fp32 softmax, fp16 message gather ----------
__global__ void gat1_kernel(const float* __restrict__ b1) {
    int node = (blockIdx.x * blockDim.x + threadIdx.x) >> 5;
    int lane = threadIdx.x & 31;
    if (node >= N_NODES) return;
    int start = g_off[node], end = g_off[node + 1];

    float4 ad = *(const float4*)&g_adst1[node * H1];

    float4 den = make_float4(0.f, 0.f, 0.f, 0.f);
    for (int idx = start + lane; idx < end; idx += 32) {
        int src = g_csr_src[idx];
        float4 as = *(const float4*)&g_asrc1[src * H1];
        float4 p;
        p.x = __expf(leaky(as.x + ad.x));
        p.y = __expf(leaky(as.y + ad.y));
        p.z = __expf(leaky(as.z + ad.z));
        p.w = __expf(leaky(as.w + ad.w));
        *(float4*)&g_p[(size_t)idx * 4] = p;
        den.x += p.x; den.y += p.y; den.z += p.z; den.w += p.w;
    }
#pragma unroll
    for (int o = 16; o > 0; o >>= 1) {
        den.x += __shfl_xor_sync(0xffffffffu, den.x, o);
        den.y += __shfl_xor_sync(0xffffffffu, den.y, o);
        den.z += __shfl_xor_sync(0xffffffffu, den.z, o);
        den.w += __shfl_xor_sync(0xffffffffu, den.w, o);
    }
    float inv0 = 1.0f / den.x, inv1 = 1.0f / den.y, inv2 = 1.0f / den.z, inv3 = 1.0f / den.w;

    float acc[6] = {0.f, 0.f, 0.f, 0.f, 0.f, 0.f};
    for (int idx = start; idx < end; idx++) {
        int src = g_csr_src[idx];
        float4 p4 = *(const float4*)&g_p[(size_t)idx * 4];
        float a0 = p4.x * inv0, a1 = p4.y * inv1, a2 = p4.z * inv2, a3 = p4.w * inv3;
        const __half* hp = &g_h1h[(size_t)src * F1];
#pragma unroll
        for (int k = 0; k < 6; k++) {
            int c = k * 32 + lane;
            float al = (c < 48) ? a0 : (c < 96) ? a1 : (c < 144) ? a2 : a3;
            acc[k] += __half2float(hp[c]) * al;
        }
    }
#pragma unroll
    for (int k = 0; k < 6; k++) {
        int c = k * 32 + lane;
        g_h1r[(size_t)node * F1 + c] = fmaxf(acc[k] + b1[c], 0.0f);
    }
}

// ---------------- layer 2 fused: fp32 softmax, fp16 message gather + pool ----
__global__ void gat2_kernel(const float* __restrict__ b2) {
    int node = (blockIdx.x * blockDim.x + threadIdx.x) >> 5;
    int lane = threadIdx.x & 31;
    if (node >= N_NODES) return;
    int start = g_off[node], end = g_off[node + 1];

    float ad = g_adst2[node];
    float den = 0.0f;
    for (int idx = start + lane; idx < end; idx += 32) {
        int src = g_csr_src[idx];
        float p = __expf(leaky(g_asrc2[src] + ad));
        g_p[idx] = p;
        den += p;
    }
#pragma unroll
    for (int o = 16; o > 0; o >>= 1) den += __shfl_xor_sync(0xffffffffu, den, o);
    float inv = 1.0f / den;

    float acc[3] = {0.f, 0.f, 0.f};
    for (int idx = start; idx < end; idx++) {
        int src = g_csr_src[idx];
        float alpha = g_p[idx] * inv;
        const __half* hp = &g_h2h[(size_t)src * C2];
#pragma unroll
        for (int k = 0; k < 3; k++) acc[k] += __half2float(hp[k * 32 + lane]) * alpha;
    }
    int gp = g_batch[node] * C2;
#pragma unroll
    for (int k = 0; k < 3; k++) {
        int c = k * 32 + lane;
        float v = fmaxf(acc[k] + b2[c], 0.0f);
        atomicAdd(&g_pool[gp + c], v);
    }
}

// ---------------- final MLP: one block per graph ----------------
__global__ void mlp_kernel(const float* __restrict__ fc1_w, const float* __restrict__ fc1_b,
                           const float* __restrict__ fc2_w, const float* __restrict__ fc2_b,
                           float* __restrict__ out) {
    __shared__ float p[C2];
    __shared__ float z[192];
    int g = blockIdx.x;
    int t = threadIdx.x;
    float inv = 1.0f / fmaxf(g_cnt[g], 1.0f);
    if (t < C2) p[t] = g_pool[g * C2 + t] * inv;
    __syncthreads();
    float acc = fc1_b[t];
#pragma unroll
    for (int k = 0; k < C2; k++) acc += p[k] * fc1_w[k * 192 + t];
    z[t] = fmaxf(acc, 0.0f);
    __syncthreads();
    if (t < C2) {
        float o = fc2_b[t];
#pragma unroll
        for (int k = 0; k < 192; k++) o += z[k] * fc2_w[k * C2 + t];
        out[g * C2 + t] = o;
    }
}

// ---------------- host launch (two-stream overlap, capture-legal) ----------
extern "C" void kernel_launch(void* const* d_in, const int* in_sizes, int n_in,
                              void* d_out, int out_size) {
    const float* x = (const float*)d_in[0];
    const void* ei_raw = d_in[1];
    const void* batch_raw = d_in[2];
    const float* W1 = (const float*)d_in[3];
    const float* a_src1 = (const float*)d_in[4];
    const float* a_dst1 = (const float*)d_in[5];
    const float* b1 = (const float*)d_in[6];
    const float* W2 = (const float*)d_in[7];
    const float* a_src2 = (const float*)d_in[8];
    const float* a_dst2 = (const float*)d_in[9];
    const float* b2 = (const float*)d_in[10];
    const float* fc1_w = (const float*)d_in[11];
    const float* fc1_b = (const float*)d_in[12];
    const float* fc2_w = (const float*)d_in[13];
    const float* fc2_b = (const float*)d_in[14];
    float* out = (float*)d_out;

    int E0 = in_sizes[1] / 2;
    int Etot = E0 + N_NODES;

    float *h1p, *h1rp, *h2p;
    __half *h1hp, *h2hp;
    cudaGetSymbolAddress((void**)&h1p, g_h1);
    cudaGetSymbolAddress((void**)&h1rp, g_h1r);
    cudaGetSymbolAddress((void**)&h2p, g_h2);
    cudaGetSymbolAddress((void**)&h1hp, g_h1h);
    cudaGetSymbolAddress((void**)&h2hp, g_h2h);

    // fork a side stream for graph preprocessing
    cudaStream_t sB;
    cudaStreamCreateWithFlags(&sB, cudaStreamNonBlocking);
    cudaEvent_t evFork, evJoin;
    cudaEventCreateWithFlags(&evFork, cudaEventDisableTiming);
    cudaEventCreateWithFlags(&evJoin, cudaEventDisableTiming);

    cudaEventRecord(evFork, 0);
    cudaStreamWaitEvent(sB, evFork, 0);

    // ---- stream B: CSR build + batch decode ----
    init_kernel<<<256, 256, 0, sB>>>();
    sniff_kernel<<<1, 256, 0, sB>>>((const unsigned int*)ei_raw);
    decode_edges<<<(Etot + 255) / 256, 256, 0, sB>>>(ei_raw, E0);
    decode_batch<<<(N_NODES + 255) / 256, 256, 0, sB>>>(batch_raw);
    scan_kernel<<<1, 1024, 0, sB>>>();
    scatter_kernel<<<(Etot + 255) / 256, 256, 0, sB>>>(Etot);
    cudaEventRecord(evJoin, sB);

    // ---- default stream: GEMM1 (+fp16 shadow) + attn1 ----
    {
        dim3 grid(F1 / 64, (N_NODES + 127) / 128);
        sgemm_kernel<128, 64, true><<<grid, 256>>>(x, W1, h1p, h1hp, N_NODES, F1, D_IN);
    }
    attn1_kernel<<<(N_NODES * H1 + 255) / 256, 256>>>(a_src1, a_dst1);

    // join: gat1 needs both chains
    cudaStreamWaitEvent(0, evJoin, 0);

    gat1_kernel<<<(N_NODES + 7) / 8, 256>>>(b1);

    // layer 2
    {
        dim3 grid(C2 / 32, (N_NODES + 255) / 256);
        sgemm_kernel<256, 32, true><<<grid, 256>>>(h1rp, W2, h2p, h2hp, N_NODES, C2, F1);
    }
    attn2_kernel<<<(N_NODES * 32 + 255) / 256, 256>>>(a_src2, a_dst2);
    gat2_kernel<<<(N_NODES + 7) / 8, 256>>>(b2);

    // MLP head
    mlp_kernel<<<NUM_GRAPHS, 192>>>(fc1_w, fc1_b, fc2_w, fc2_b, out);
}